// round 14
// baseline (speedup 1.0000x reference)
#include <cuda_runtime.h>
#include <cuda_fp16.h>
#include <math.h>

typedef unsigned int uint;

#define BATCH 2048
#define WID 24
#define PIX 168            // 7*24
#define C0IN 2
#define HC0 32
#define HC1 64

#define P1ROW 26           // padded cols (24 + halo)
#define NCH0 18            // layer0: 9 taps * 2 ic16-chunks
#define NCH1 54            // layer1: 9 taps * 6 ic16-chunks

// persistent-kernel SMEM layout (bytes)
#define PH0_OFF 0
#define PH0_B   (9*P1ROW*32*2)         // 14976  h0 plane [cell][32]
#define PH1_OFF PH0_B
#define PH1_STRIDE (9*P1ROW*64*2)      // 29952  one h1 buffer [cell][64]
#define PH1_B   (2*PH1_STRIDE)         // 59904  double-buffered
#define C0_OFF  (PH1_OFF+PH1_B)        // 74880
#define C0_B    (PIX*33*4)             // 22176
#define C1_OFF  (C0_OFF+C0_B)          // 97056
#define C1_B    (PIX*65*4)             // 43680
#define GX_OFF  (C1_OFF+C1_B)          // 140736
#define GX_B    (PIX*128*4)            // 86016
#define SMEM_TOT (GX_OFF+GX_B)         // 226752

// ---------------- scratch ----------------
__device__ float  g_gx0[(size_t)BATCH * PIX * 128];     // [item][pix][hc*4+g], bias included
__device__ __half g_h1out[(size_t)BATCH * PIX * HC1];   // final h1, [item][pix][hc]
__device__ float  g_fcwT[10752 * 64];
__device__ __align__(16) __half g_w0h[NCH0 * 16 * 128]; // staging [chunk][k16][n]
__device__ __align__(16) __half g_w1h[NCH1 * 16 * 256];
// mma B-fragment layouts: [chunk][n8pair][lane][4 x b32]
__device__ __align__(16) uint g_w0f[NCH0 * 8 * 32 * 4];
__device__ __align__(16) uint g_w1f[NCH1 * 16 * 32 * 4];

// ---------------- helpers ----------------
__device__ __forceinline__ float sigf(float x) { return 0.5f * tanhf(0.5f * x) + 0.5f; }
__device__ __forceinline__ uint smem_u32(const void* p) {
    uint a;
    asm("{ .reg .u64 t; cvta.to.shared.u64 t, %1; cvt.u32.u64 %0, t; }" : "=r"(a) : "l"(p));
    return a;
}
__device__ __forceinline__ void ldsmx4(uint* a, uint addr) {
    asm volatile("ldmatrix.sync.aligned.m8n8.x4.shared.b16 {%0,%1,%2,%3}, [%4];"
                 : "=r"(a[0]), "=r"(a[1]), "=r"(a[2]), "=r"(a[3]) : "r"(addr));
}
#define MMA(Dp, Ap, b0v, b1v) \
    asm volatile("mma.sync.aligned.m16n8k16.row.col.f32.f16.f16.f32 " \
                 "{%0,%1,%2,%3}, {%4,%5,%6,%7}, {%8,%9}, {%0,%1,%2,%3};" \
                 : "+f"((Dp)[0]), "+f"((Dp)[1]), "+f"((Dp)[2]), "+f"((Dp)[3]) \
                 : "r"((Ap)[0]), "r"((Ap)[1]), "r"((Ap)[2]), "r"((Ap)[3]), \
                   "r"(b0v), "r"(b1v))

// ---------------- weight transforms (k-major staging layout) ----------------
__global__ void k_w0h(const float* __restrict__ Wh0) {
    int idx = blockIdx.x * blockDim.x + threadIdx.x;
    if (idx >= NCH0 * 16 * 128) return;
    int chunk = idx / 2048, rem = idx % 2048;
    int k = rem / 128, n = rem % 128;
    int tap = chunk >> 1, icc = chunk & 1;
    int ic = icc * 16 + k;
    int hc = n >> 2, g = n & 3;
    g_w0h[idx] = __float2half(Wh0[((g * HC0 + hc) * HC0 + ic) * 9 + tap]);
}

__global__ void k_w1h(const float* __restrict__ Wx1, const float* __restrict__ Wh1) {
    int idx = blockIdx.x * blockDim.x + threadIdx.x;
    if (idx >= NCH1 * 16 * 256) return;
    int chunk = idx / 4096, rem = idx % 4096;
    int k = rem / 256, n = rem % 256;
    int tap = chunk / 6, icc = chunk % 6;
    int ic = icc * 16 + k;
    int hc = n / 4, g = n % 4;
    float v = (ic < HC0) ? Wx1[((g * HC1 + hc) * HC0 + ic) * 9 + tap]
                         : Wh1[((g * HC1 + hc) * HC1 + (ic - HC0)) * 9 + tap];
    g_w1h[idx] = __float2half(v);
}

// ---------------- fragmentizers: k-major -> mma B-fragment order ----------------
__global__ void k_w0f() {
    int idx = blockIdx.x * blockDim.x + threadIdx.x;
    if (idx >= NCH0 * 8 * 32 * 4) return;
    int q = idx & 3, l = (idx >> 2) & 31, pp = (idx >> 7) & 7, c = idx >> 10;
    int tt = pp * 2 + (q >> 1), r = q & 1;
    int k0 = (l & 3) * 2 + r * 8, n = tt * 8 + (l >> 2);
    __half h0 = g_w0h[c * 2048 + k0 * 128 + n];
    __half h1 = g_w0h[c * 2048 + (k0 + 1) * 128 + n];
    ((__half2*)g_w0f)[idx] = __halves2half2(h0, h1);
}

__global__ void k_w1f() {
    int idx = blockIdx.x * blockDim.x + threadIdx.x;
    if (idx >= NCH1 * 16 * 32 * 4) return;
    int q = idx & 3, l = (idx >> 2) & 31, pp = (idx >> 7) & 15, c = idx >> 11;
    int tt = pp * 2 + (q >> 1), r = q & 1;
    int k0 = (l & 3) * 2 + r * 8, n = tt * 8 + (l >> 2);
    __half h0 = g_w1h[c * 4096 + k0 * 256 + n];
    __half h1 = g_w1h[c * 4096 + (k0 + 1) * 256 + n];
    ((__half2*)g_w1f)[idx] = __halves2half2(h0, h1);
}

// ---------------- gx0 = conv(input, Wx0) + bx0, layout [pix][hc*4+g] ----------------
#define SROW0 28
#define SPLANE0 (9*SROW0)
__global__ void k_gx0(const float* __restrict__ input, const float* __restrict__ Wx0,
                      const float* __restrict__ bx0) {
    __shared__ float sin_[C0IN * SPLANE0];
    int b = blockIdx.x, tid = threadIdx.x;
    for (int i = tid; i < C0IN * SPLANE0; i += blockDim.x) sin_[i] = 0.f;
    __syncthreads();
    for (int u = tid; u < C0IN * PIX; u += blockDim.x) {
        int ic = u / PIX, pix = u % PIX, y = pix / WID, x = pix % WID;
        sin_[ic * SPLANE0 + (y + 1) * SROW0 + (x + 1)] = input[(size_t)b * C0IN * PIX + u];
    }
    __syncthreads();
    for (int u = tid; u < 128 * PIX; u += blockDim.x) {
        int oc = u / PIX, pix = u % PIX, y = pix / WID, x = pix % WID;
        float acc = bx0[oc];
#pragma unroll
        for (int ic = 0; ic < C0IN; ic++)
#pragma unroll
            for (int ky = 0; ky < 3; ky++)
#pragma unroll
                for (int kx = 0; kx < 3; kx++)
                    acc += sin_[ic * SPLANE0 + (y + ky) * SROW0 + (x + kx)] *
                           __ldg(&Wx0[oc * 18 + ic * 9 + ky * 3 + kx]);
        int g = oc >> 5, hc = oc & 31;
        g_gx0[(size_t)b * PIX * 128 + pix * 128 + hc * 4 + g] = acc;
    }
}

// ---------------- persistent 7-step dual-layer cell kernel ----------------
__global__ void __launch_bounds__(512, 1)
k_cells(const float* __restrict__ bx1, const float* __restrict__ Wc0,
        const float* __restrict__ Wc1) {
    extern __shared__ __align__(16) char sm[];
    __half* ph0  = (__half*)(sm + PH0_OFF);              // [cell][32]
    float*  c0s  = (float*)(sm + C0_OFF);                // [pix][33]
    float*  c1s  = (float*)(sm + C1_OFF);                // [pix][65]
    float*  sgx  = (float*)(sm + GX_OFF);                // [pix][128]

    int b = blockIdx.x, tid = threadIdx.x;
    int lane = tid & 31, warp = tid >> 5;
    int mg = warp >> 2, ng = warp & 3;
    int ntl = (mg == 3) ? 2 : 3;
    int tbase = (mg == 3) ? 9 : mg * 3;

    // ---- zero state region; stage gx into smem ----
    uint4 z4; z4.x = z4.y = z4.z = z4.w = 0u;
    for (int i = tid; i < GX_OFF / 16; i += 512) ((uint4*)sm)[i] = z4;
    {
        const uint4* gsrc = (const uint4*)(g_gx0 + (size_t)b * PIX * 128);
        uint4* gdst = (uint4*)sgx;
        for (int i = tid; i < GX_B / 16; i += 512) gdst[i] = gsrc[i];
    }
    __syncthreads();

    uint pl0U = smem_u32(sm + PH0_OFF);
    uint ph1baseU = smem_u32(sm + PH1_OFF);

    int base26[3];
    base26[0] = base26[1] = base26[2] = P1ROW + 1;
#pragma unroll
    for (int mt = 0; mt < 3; mt++) {
        if (mt < ntl) {
            int p = (tbase + mt) * 16 + (lane & 15);
            if (p > 167) p = 167;
            base26[mt] = (p / WID + 1) * P1ROW + (p % WID + 1);
        }
    }
    uint ahi = (uint)((lane >> 4) * 16);
    int t = lane & 3, r = lane >> 2, odd = t & 1;

#pragma unroll 1
    for (int s = 0; s < 7; s++) {
        int src = s & 1, dst = src ^ 1;
        uint ph1sU = ph1baseU + (uint)(src * PH1_STRIDE);
        __half* ph1d = (__half*)(sm + PH1_OFF + dst * PH1_STRIDE);

        // ================= Phase A: layer 0 (N=128) =================
        {
            float d0[3][4][4];
#pragma unroll
            for (int mt = 0; mt < 3; mt++)
#pragma unroll
                for (int j = 0; j < 4; j++)
#pragma unroll
                    for (int q = 0; q < 4; q++) d0[mt][j][q] = 0.f;

            uint aA[2][3][4];
            uint4 wA[2][2];

#define PRE_A(c_, buf_) do { \
    int tap_ = (c_) >> 1, icc_ = (c_) & 1; \
    int toff_ = (tap_ / 3 - 1) * P1ROW + (tap_ % 3 - 1); \
    _Pragma("unroll") for (int mt_ = 0; mt_ < 3; mt_++) if (mt_ < ntl) \
        ldsmx4(aA[buf_][mt_], pl0U + (uint)((base26[mt_] + toff_) * 64) + \
               (uint)(icc_ * 32) + ahi); \
    const uint4* fp_ = (const uint4*)g_w0f + (size_t)(((c_) * 8 + ng * 2) * 32) + lane; \
    wA[buf_][0] = __ldg(fp_); wA[buf_][1] = __ldg(fp_ + 32); \
} while (0)

#define MMA_A(buf_) do { \
    _Pragma("unroll") for (int j_ = 0; j_ < 2; j_++) { \
        uint4 w_ = wA[buf_][j_]; \
        _Pragma("unroll") for (int mt_ = 0; mt_ < 3; mt_++) if (mt_ < ntl) { \
            MMA(d0[mt_][2 * j_], aA[buf_][mt_], w_.x, w_.y); \
            MMA(d0[mt_][2 * j_ + 1], aA[buf_][mt_], w_.z, w_.w); } } \
} while (0)

            PRE_A(0, 0);
#pragma unroll 1
            for (int c = 0; c < NCH0; c += 2) {
                if (c + 1 < NCH0) PRE_A(c + 1, 1);
                MMA_A(0);
                if (c + 2 < NCH0) PRE_A(c + 2, 0);
                if (c + 1 < NCH0) MMA_A(1);
            }
            __syncthreads();   // all phase-A/prev-B reads of planes done

            // ---- epilogue A: gates -> c0 (SMEM), h0 -> ph0 in place ----
#pragma unroll
            for (int mt = 0; mt < 3; mt++) {
                if (mt >= ntl) continue;
                int tile = tbase + mt;
#pragma unroll
                for (int j = 0; j < 4; j++) {
                    float v0 = d0[mt][j][0], v1 = d0[mt][j][1];
                    float v2 = d0[mt][j][2], v3 = d0[mt][j][3];
                    float x0 = __shfl_xor_sync(0xffffffffu, v0, 1);
                    float x1 = __shfl_xor_sync(0xffffffffu, v1, 1);
                    float x2 = __shfl_xor_sync(0xffffffffu, v2, 1);
                    float x3 = __shfl_xor_sync(0xffffffffu, v3, 1);
                    int pixel = tile * 16 + r + odd * 8;
                    int hc = ng * 8 + j * 2 + (t >> 1);
                    float gi = odd ? x2 : v0;
                    float gf = odd ? x3 : v1;
                    float gc = odd ? v2 : x0;
                    float go = odd ? v3 : x1;
                    if (pixel < PIX) {
                        float4 gx = *(const float4*)(sgx + pixel * 128 + hc * 4);
                        gi += gx.x; gf += gx.y; gc += gx.z; go += gx.w;
                        float cold = c0s[pixel * 33 + hc];
                        float w0 = __ldg(&Wc0[hc * PIX + pixel]);
                        float w1 = __ldg(&Wc0[HC0 * PIX + hc * PIX + pixel]);
                        float w2 = __ldg(&Wc0[2 * HC0 * PIX + hc * PIX + pixel]);
                        float ci = sigf(gi + cold * w0);
                        float cf = sigf(gf + cold * w1);
                        float cc = cf * cold + ci * tanhf(gc);
                        float co = sigf(go + cc * w2);
                        c0s[pixel * 33 + hc] = cc;
                        int y = pixel / WID, x = pixel % WID;
                        ph0[((y + 1) * P1ROW + (x + 1)) * HC0 + hc] =
                            __float2half(co * tanhf(cc));
                    }
                }
            }
        }
        __syncthreads();   // h0 visible before phase B reads

        // ================= Phase B: layer 1, two N-halves =================
        __half* h1g = g_h1out + (size_t)b * PIX * HC1;
#pragma unroll 1
        for (int h = 0; h < 2; h++) {
            float dB[3][4][4];
#pragma unroll
            for (int mt = 0; mt < 3; mt++)
#pragma unroll
                for (int j = 0; j < 4; j++)
#pragma unroll
                    for (int q = 0; q < 4; q++) dB[mt][j][q] = 0.f;

            uint aB[2][3][4];
            uint4 wB[2][2];

#define PRE_B(c_, buf_) do { \
    int tap_ = (c_) / 6, icc_ = (c_) % 6; \
    int toff_ = (tap_ / 3 - 1) * P1ROW + (tap_ % 3 - 1); \
    _Pragma("unroll") for (int mt_ = 0; mt_ < 3; mt_++) if (mt_ < ntl) { \
        int cell_ = base26[mt_] + toff_; \
        uint ad_ = (icc_ < 2) ? (pl0U + (uint)(cell_ * 64) + (uint)(icc_ * 32) + ahi) \
                              : (ph1sU + (uint)(cell_ * 128) + (uint)((icc_ - 2) * 32) + ahi); \
        ldsmx4(aB[buf_][mt_], ad_); } \
    const uint4* fp_ = (const uint4*)g_w1f + \
        (size_t)(((c_) * 16 + h * 8 + ng * 2) * 32) + lane; \
    wB[buf_][0] = __ldg(fp_); wB[buf_][1] = __ldg(fp_ + 32); \
} while (0)

#define MMA_B(buf_) do { \
    _Pragma("unroll") for (int j_ = 0; j_ < 2; j_++) { \
        uint4 w_ = wB[buf_][j_]; \
        _Pragma("unroll") for (int mt_ = 0; mt_ < 3; mt_++) if (mt_ < ntl) { \
            MMA(dB[mt_][2 * j_], aB[buf_][mt_], w_.x, w_.y); \
            MMA(dB[mt_][2 * j_ + 1], aB[buf_][mt_], w_.z, w_.w); } } \
} while (0)

            PRE_B(0, 0);
#pragma unroll 1
            for (int c = 0; c < NCH1; c += 2) {
                if (c + 1 < NCH1) PRE_B(c + 1, 1);
                MMA_B(0);
                if (c + 2 < NCH1) PRE_B(c + 2, 0);
                if (c + 1 < NCH1) MMA_B(1);
            }

            // ---- epilogue B half: gates -> c1 (SMEM), h1 -> ph1[dst] ----
            // no barrier needed: reads were from ph1[src]/ph0, writes go to ph1[dst]
#pragma unroll
            for (int mt = 0; mt < 3; mt++) {
                if (mt >= ntl) continue;
                int tile = tbase + mt;
#pragma unroll
                for (int j = 0; j < 4; j++) {
                    float v0 = dB[mt][j][0], v1 = dB[mt][j][1];
                    float v2 = dB[mt][j][2], v3 = dB[mt][j][3];
                    float x0 = __shfl_xor_sync(0xffffffffu, v0, 1);
                    float x1 = __shfl_xor_sync(0xffffffffu, v1, 1);
                    float x2 = __shfl_xor_sync(0xffffffffu, v2, 1);
                    float x3 = __shfl_xor_sync(0xffffffffu, v3, 1);
                    int pixel = tile * 16 + r + odd * 8;
                    int hc = h * 32 + ng * 8 + j * 2 + (t >> 1);
                    float gi = odd ? x2 : v0;
                    float gf = odd ? x3 : v1;
                    float gc = odd ? v2 : x0;
                    float go = odd ? v3 : x1;
                    if (pixel < PIX) {
                        gi += __ldg(&bx1[hc]);
                        gf += __ldg(&bx1[64 + hc]);
                        gc += __ldg(&bx1[128 + hc]);
                        go += __ldg(&bx1[192 + hc]);
                        float cold = c1s[pixel * 65 + hc];
                        float w0 = __ldg(&Wc1[hc * PIX + pixel]);
                        float w1 = __ldg(&Wc1[10752 + hc * PIX + pixel]);
                        float w2 = __ldg(&Wc1[21504 + hc * PIX + pixel]);
                        float ci = sigf(gi + cold * w0);
                        float cf = sigf(gf + cold * w1);
                        float cc = cf * cold + ci * tanhf(gc);
                        float co = sigf(go + cc * w2);
                        c1s[pixel * 65 + hc] = cc;
                        __half hh = __float2half(co * tanhf(cc));
                        int y = pixel / WID, x = pixel % WID;
                        ph1d[((y + 1) * P1ROW + (x + 1)) * HC1 + hc] = hh;
                        if (s == 6) h1g[pixel * HC1 + hc] = hh;
                    }
                }
            }
        }
        // next step's first barrier (after its phase-A K-loop) orders
        // this step's ph1[dst] writes against next step's phase-B reads
    }
}

// ---------------- fc1 weight transpose: k follows [pix][ch] flatten ----------------
__global__ void k_wt(const float* __restrict__ fc1_w) {
    int idx = blockIdx.x * blockDim.x + threadIdx.x;
    if (idx >= 10752 * 64) return;
    int k = idx / 64, o = idx % 64;       // k = pix*64 + ch
    int pix = k / 64, ch = k % 64;
    g_fcwT[k * 64 + (o & 31) * 2 + (o >> 5)] = fc1_w[(size_t)o * 10752 + ch * PIX + pix];
}

// ---------------- fc1 head: out[:, 0:64] ----------------
__global__ void k_fc(const float* __restrict__ fc1_b, float* __restrict__ out) {
    __shared__ float shh[8 * 1344];
    int tid = threadIdx.x;
    int b0 = blockIdx.x * 8;
    int it = tid >> 5, o = tid & 31;
    float acc0 = 0.f, acc1 = 0.f;
    const __half* h1f = g_h1out;
#pragma unroll 1
    for (int cb = 0; cb < 8; cb++) {
        __syncthreads();
        for (int u = tid; u < 8 * 1344; u += 256) {
            int i2 = u / 1344, kk = u % 1344;
            shh[u] = __half2float(h1f[(size_t)(b0 + i2) * 10752 + cb * 1344 + kk]);
        }
        __syncthreads();
        const float* wp = g_fcwT + (size_t)cb * 1344 * 64 + o * 2;
        const float* hp = shh + it * 1344;
#pragma unroll 4
        for (int kk = 0; kk < 1344; kk++) {
            float hv = hp[kk];
            float2 w2 = __ldg((const float2*)(wp + (size_t)kk * 64));
            acc0 = fmaf(hv, w2.x, acc0);
            acc1 = fmaf(hv, w2.y, acc1);
        }
    }
    out[(size_t)(b0 + it) * 128 + o] = fmaxf(acc0 + fc1_b[o], 0.f);
    out[(size_t)(b0 + it) * 128 + o + 32] = fmaxf(acc1 + fc1_b[o + 32], 0.f);
}

// ---------------- exfc head: out[:, 64:128] ----------------
__global__ void k_exfc(const float* __restrict__ x_ex, const float* __restrict__ w,
                       const float* __restrict__ bias, float* __restrict__ out) {
    int idx = blockIdx.x * blockDim.x + threadIdx.x;
    if (idx >= BATCH * 64) return;
    int b = idx >> 6, o = idx & 63;
    float acc = bias[o];
#pragma unroll
    for (int k = 0; k < 24; k++) acc += x_ex[b * 24 + k] * __ldg(&w[o * 24 + k]);
    out[(size_t)b * 128 + 64 + o] = fmaxf(acc, 0.f);
}

// ---------------- launch ----------------
extern "C" void kernel_launch(void* const* d_in, const int* in_sizes, int n_in,
                              void* d_out, int out_size) {
    const float* input  = (const float*)d_in[0];
    const float* x_ex   = (const float*)d_in[1];
    const float* Wx0    = (const float*)d_in[2];
    const float* bx0    = (const float*)d_in[3];
    const float* Wh0    = (const float*)d_in[4];
    const float* Wc0    = (const float*)d_in[5];
    const float* Wx1    = (const float*)d_in[6];
    const float* bx1    = (const float*)d_in[7];
    const float* Wh1    = (const float*)d_in[8];
    const float* Wc1    = (const float*)d_in[9];
    const float* fc1_w  = (const float*)d_in[10];
    const float* fc1_b  = (const float*)d_in[11];
    const float* exfc_w = (const float*)d_in[12];
    const float* exfc_b = (const float*)d_in[13];
    float* out = (float*)d_out;

    (void)in_sizes; (void)n_in; (void)out_size;

    cudaFuncSetAttribute(k_cells, cudaFuncAttributeMaxDynamicSharedMemorySize, SMEM_TOT);

    k_gx0<<<BATCH, 256>>>(input, Wx0, bx0);
    k_wt<<<(10752 * 64 + 255) / 256, 256>>>(fc1_w);
    k_w0h<<<(NCH0 * 16 * 128 + 255) / 256, 256>>>(Wh0);
    k_w1h<<<(NCH1 * 16 * 256 + 255) / 256, 256>>>(Wx1, Wh1);
    k_w0f<<<(NCH0 * 8 * 32 * 4 + 255) / 256, 256>>>();
    k_w1f<<<(NCH1 * 16 * 32 * 4 + 255) / 256, 256>>>();

    k_cells<<<BATCH, 512, SMEM_TOT>>>(bx1, Wc0, Wc1);

    k_fc<<<BATCH / 8, 256>>>(fc1_b, out);
    k_exfc<<<(BATCH * 64 + 255) / 256, 256>>>(x_ex, exfc_w, exfc_b, out);
}

// round 15
// speedup vs baseline: 1.4177x; 1.4177x over previous
#include <cuda_runtime.h>
#include <cuda_fp16.h>
#include <math.h>

typedef unsigned long long ull;
typedef unsigned int uint;

#define BATCH 2048
#define HGT 7
#define WID 24
#define PIX 168            // 7*24
#define C0IN 2
#define HC0 32
#define HC1 64

// tensor-core geometry
#define P1ROW 26           // padded cols (24 + halo)
#define P1CH 96            // cell1 plane channels (32 h0 + 64 h1)
#define NCH1 54            // cell1: 9 taps * 6 ic16-chunks
#define NCH0 18            // cell0: 9 taps * 2 ic16-chunks

// persistent-kernel SMEM layout (bytes)
#define PL1_BYTES (9*P1ROW*P1CH*2)   // 44928
#define PL0_BYTES (9*P1ROW*HC0*2)    // 14976
#define C0_BYTES  (PIX*33*4)         // 22176 (pad 32->33: bank-conflict-free)
#define C1_BYTES  (PIX*65*4)         // 43680 (pad 64->65)
#define SMEM_TOT  (PL1_BYTES + PL0_BYTES + C0_BYTES + C1_BYTES)   // 125760

// ---------------- scratch ----------------
__device__ float  g_gx0[(size_t)BATCH * PIX * 128];     // [item][pix][hc*4+g], bias included
__device__ __half g_h1out[(size_t)BATCH * PIX * HC1];   // final h1, [item][pix][hc]
__device__ float  g_fcwT[10752 * 64];
__device__ __align__(16) __half g_w0h[NCH0 * 16 * 128]; // staging [chunk][k16][n]
__device__ __align__(16) __half g_w1h[NCH1 * 16 * 256];
// mma B-fragment layouts: [chunk][n8pair][lane][4 x b32]
__device__ __align__(16) uint g_w0f[NCH0 * 8 * 32 * 4];
__device__ __align__(16) uint g_w1f[NCH1 * 16 * 32 * 4];

// ---------------- helpers ----------------
__device__ __forceinline__ float sigf(float x) { return 0.5f * tanhf(0.5f * x) + 0.5f; }
__device__ __forceinline__ uint smem_u32(const void* p) {
    uint a;
    asm("{ .reg .u64 t; cvta.to.shared.u64 t, %1; cvt.u32.u64 %0, t; }" : "=r"(a) : "l"(p));
    return a;
}

// ---------------- weight transforms (k-major staging layout) ----------------
__global__ void k_w0h(const float* __restrict__ Wh0) {
    int idx = blockIdx.x * blockDim.x + threadIdx.x;
    if (idx >= NCH0 * 16 * 128) return;
    int chunk = idx / 2048, rem = idx % 2048;
    int k = rem / 128, n = rem % 128;
    int tap = chunk >> 1, icc = chunk & 1;
    int ic = icc * 16 + k;
    int hc = n >> 2, g = n & 3;
    g_w0h[idx] = __float2half(Wh0[((g * HC0 + hc) * HC0 + ic) * 9 + tap]);
}

__global__ void k_w1h(const float* __restrict__ Wx1, const float* __restrict__ Wh1) {
    int idx = blockIdx.x * blockDim.x + threadIdx.x;
    if (idx >= NCH1 * 16 * 256) return;
    int chunk = idx / 4096, rem = idx % 4096;
    int k = rem / 256, n = rem % 256;
    int tap = chunk / 6, icc = chunk % 6;
    int ic = icc * 16 + k;
    int hc = n / 4, g = n % 4;
    float v = (ic < HC0) ? Wx1[((g * HC1 + hc) * HC0 + ic) * 9 + tap]
                         : Wh1[((g * HC1 + hc) * HC1 + (ic - HC0)) * 9 + tap];
    g_w1h[idx] = __float2half(v);
}

// ---------------- fragmentizers: k-major -> mma B-fragment order ----------------
__global__ void k_w0f() {
    int idx = blockIdx.x * blockDim.x + threadIdx.x;
    if (idx >= NCH0 * 8 * 32 * 4) return;
    int q = idx & 3, l = (idx >> 2) & 31, pp = (idx >> 7) & 7, c = idx >> 10;
    int tt = pp * 2 + (q >> 1), r = q & 1;
    int k0 = (l & 3) * 2 + r * 8, n = tt * 8 + (l >> 2);
    __half h0 = g_w0h[c * 2048 + k0 * 128 + n];
    __half h1 = g_w0h[c * 2048 + (k0 + 1) * 128 + n];
    ((__half2*)g_w0f)[idx] = __halves2half2(h0, h1);
}

__global__ void k_w1f() {
    int idx = blockIdx.x * blockDim.x + threadIdx.x;
    if (idx >= NCH1 * 16 * 32 * 4) return;
    int q = idx & 3, l = (idx >> 2) & 31, pp = (idx >> 7) & 15, c = idx >> 11;
    int tt = pp * 2 + (q >> 1), r = q & 1;
    int k0 = (l & 3) * 2 + r * 8, n = tt * 8 + (l >> 2);
    __half h0 = g_w1h[c * 4096 + k0 * 256 + n];
    __half h1 = g_w1h[c * 4096 + (k0 + 1) * 256 + n];
    ((__half2*)g_w1f)[idx] = __halves2half2(h0, h1);
}

// ---------------- gx0 = conv(input, Wx0) + bx0, layout [pix][hc*4+g] ----------------
#define SROW0 28
#define SPLANE0 (9*SROW0)
__global__ void k_gx0(const float* __restrict__ input, const float* __restrict__ Wx0,
                      const float* __restrict__ bx0) {
    __shared__ float sin_[C0IN * SPLANE0];
    int b = blockIdx.x, tid = threadIdx.x;
    for (int i = tid; i < C0IN * SPLANE0; i += blockDim.x) sin_[i] = 0.f;
    __syncthreads();
    for (int u = tid; u < C0IN * PIX; u += blockDim.x) {
        int ic = u / PIX, pix = u % PIX, y = pix / WID, x = pix % WID;
        sin_[ic * SPLANE0 + (y + 1) * SROW0 + (x + 1)] = input[(size_t)b * C0IN * PIX + u];
    }
    __syncthreads();
    for (int u = tid; u < 128 * PIX; u += blockDim.x) {
        int oc = u / PIX, pix = u % PIX, y = pix / WID, x = pix % WID;
        float acc = bx0[oc];
#pragma unroll
        for (int ic = 0; ic < C0IN; ic++)
#pragma unroll
            for (int ky = 0; ky < 3; ky++)
#pragma unroll
                for (int kx = 0; kx < 3; kx++)
                    acc += sin_[ic * SPLANE0 + (y + ky) * SROW0 + (x + kx)] *
                           __ldg(&Wx0[oc * 18 + ic * 9 + ky * 3 + kx]);
        int g = oc >> 5, hc = oc & 31;
        g_gx0[(size_t)b * PIX * 128 + pix * 128 + hc * 4 + g] = acc;
    }
}

// ---------------- persistent 7-step dual-layer cell kernel ----------------
__global__ void __launch_bounds__(512, 1)
k_cells(const float* __restrict__ bx1, const float* __restrict__ Wc0,
        const float* __restrict__ Wc1) {
    extern __shared__ __align__(16) char smraw[];
    __half* plane1 = (__half*)smraw;                                  // [9][26][96]
    __half* plane0 = (__half*)(smraw + PL1_BYTES);                    // [9][26][32]
    float*  c0s    = (float*)(smraw + PL1_BYTES + PL0_BYTES);         // [pix][33]
    float*  c1s    = (float*)(smraw + PL1_BYTES + PL0_BYTES + C0_BYTES); // [pix][65]

    int b = blockIdx.x, tid = threadIdx.x;
    int lane = tid & 31, warp = tid >> 5;
    int mg = warp >> 2, ng = warp & 3;
    // 11 M-tiles: warps mg<3 own tiles [3mg,3mg+2], mg==3 owns tiles [9,10]
    int ntl = (mg == 3) ? 2 : 3;
    int tbase = (mg == 3) ? 9 : mg * 3;

    // ---- zero entire SMEM state (planes incl. halos, c-states) once ----
    uint4 z4; z4.x = z4.y = z4.z = z4.w = 0u;
    for (int i = tid; i < SMEM_TOT / 16; i += 512) ((uint4*)smraw)[i] = z4;
    __syncthreads();

    uint pl1U = smem_u32(plane1);
    uint pl0U = smem_u32(plane0);

    int base26[3];
#pragma unroll
    for (int mt = 0; mt < 3; mt++) {
        int p = (tbase + ((mt < ntl) ? mt : 0)) * 16 + (lane & 15);
        if (p > 167) p = 167;
        base26[mt] = (p / WID + 1) * P1ROW + (p % WID + 1);
    }
    uint ahi = (uint)((lane >> 4) * 16);
    int t = lane & 3, r = lane >> 2, odd = t & 1;

    const float* gx0p = g_gx0 + (size_t)b * PIX * 128;

#pragma unroll 1
    for (int s = 0; s < 7; s++) {
        // ================= Phase A: layer 0 =================
        {
            float d0[3][4][4];
#pragma unroll
            for (int mt = 0; mt < 3; mt++)
#pragma unroll
                for (int j = 0; j < 4; j++)
#pragma unroll
                    for (int q = 0; q < 4; q++) d0[mt][j][q] = 0.f;

#pragma unroll 1
            for (int c = 0; c < NCH0; c++) {
                int tap = c >> 1, icc = c & 1;
                int tapoff = (tap / 3 - 1) * P1ROW + (tap % 3 - 1);
                uint a[3][4];
#pragma unroll
                for (int mt = 0; mt < 3; mt++) {
                    if (mt >= ntl) continue;
                    uint aaddr = pl0U + (uint)((base26[mt] + tapoff) * (HC0 * 2)) +
                                 (uint)(icc * 32) + ahi;
                    asm volatile("ldmatrix.sync.aligned.m8n8.x4.shared.b16 {%0,%1,%2,%3}, [%4];"
                                 : "=r"(a[mt][0]), "=r"(a[mt][1]), "=r"(a[mt][2]), "=r"(a[mt][3])
                                 : "r"(aaddr));
                }
                const uint4* fp = (const uint4*)g_w0f + (size_t)(c * 8 + ng * 2) * 32 + lane;
#pragma unroll
                for (int j = 0; j < 2; j++) {
                    uint4 v = __ldg(fp + j * 32);
#pragma unroll
                    for (int mt = 0; mt < 3; mt++) {
                        if (mt >= ntl) continue;
                        asm volatile("mma.sync.aligned.m16n8k16.row.col.f32.f16.f16.f32 "
                                     "{%0,%1,%2,%3}, {%4,%5,%6,%7}, {%8,%9}, {%0,%1,%2,%3};"
                                     : "+f"(d0[mt][2 * j][0]), "+f"(d0[mt][2 * j][1]),
                                       "+f"(d0[mt][2 * j][2]), "+f"(d0[mt][2 * j][3])
                                     : "r"(a[mt][0]), "r"(a[mt][1]), "r"(a[mt][2]), "r"(a[mt][3]),
                                       "r"(v.x), "r"(v.y));
                        asm volatile("mma.sync.aligned.m16n8k16.row.col.f32.f16.f16.f32 "
                                     "{%0,%1,%2,%3}, {%4,%5,%6,%7}, {%8,%9}, {%0,%1,%2,%3};"
                                     : "+f"(d0[mt][2 * j + 1][0]), "+f"(d0[mt][2 * j + 1][1]),
                                       "+f"(d0[mt][2 * j + 1][2]), "+f"(d0[mt][2 * j + 1][3])
                                     : "r"(a[mt][0]), "r"(a[mt][1]), "r"(a[mt][2]), "r"(a[mt][3]),
                                       "r"(v.z), "r"(v.w));
                    }
                }
            }
            __syncthreads();   // all reads of plane0 done before in-place h0 update

            // ---- epilogue A: gates -> c0 (SMEM), h0 -> plane0 + plane1 ch0-31 ----
#pragma unroll
            for (int mt = 0; mt < 3; mt++) {
                if (mt >= ntl) continue;
                int tile = tbase + mt;
#pragma unroll
                for (int j = 0; j < 4; j++) {
                    float v0 = d0[mt][j][0], v1 = d0[mt][j][1], v2 = d0[mt][j][2], v3 = d0[mt][j][3];
                    float x0 = __shfl_xor_sync(0xffffffffu, v0, 1);
                    float x1 = __shfl_xor_sync(0xffffffffu, v1, 1);
                    float x2 = __shfl_xor_sync(0xffffffffu, v2, 1);
                    float x3 = __shfl_xor_sync(0xffffffffu, v3, 1);
                    int pixel = tile * 16 + r + odd * 8;
                    int hc = ng * 8 + j * 2 + (t >> 1);
                    float gi = odd ? x2 : v0;
                    float gf = odd ? x3 : v1;
                    float gc = odd ? v2 : x0;
                    float go = odd ? v3 : x1;
                    if (pixel < PIX) {
                        float4 gx = __ldg((const float4*)(gx0p + pixel * 128 + hc * 4));
                        gi += gx.x; gf += gx.y; gc += gx.z; go += gx.w;
                        float cold = c0s[pixel * 33 + hc];
                        float w0 = __ldg(&Wc0[hc * PIX + pixel]);
                        float w1 = __ldg(&Wc0[HC0 * PIX + hc * PIX + pixel]);
                        float w2 = __ldg(&Wc0[2 * HC0 * PIX + hc * PIX + pixel]);
                        float ci = sigf(gi + cold * w0);
                        float cf = sigf(gf + cold * w1);
                        float cc = cf * cold + ci * tanhf(gc);
                        float co = sigf(go + cc * w2);
                        c0s[pixel * 33 + hc] = cc;
                        __half hh = __float2half(co * tanhf(cc));
                        int y = pixel / WID, x = pixel % WID;
                        int cell = (y + 1) * P1ROW + (x + 1);
                        plane0[cell * HC0 + hc] = hh;
                        plane1[cell * P1CH + hc] = hh;
                    }
                }
            }
        }
        __syncthreads();   // h0_new visible in plane1 before phase B reads

        // ================= Phase B: layer 1 =================
        {
            float d1[3][8][4];
#pragma unroll
            for (int mt = 0; mt < 3; mt++)
#pragma unroll
                for (int j = 0; j < 8; j++)
#pragma unroll
                    for (int q = 0; q < 4; q++) d1[mt][j][q] = 0.f;

#pragma unroll 1
            for (int c = 0; c < NCH1; c++) {
                int tap = c / 6, icc = c % 6;
                int tapoff = (tap / 3 - 1) * P1ROW + (tap % 3 - 1);
                uint a[3][4];
#pragma unroll
                for (int mt = 0; mt < 3; mt++) {
                    if (mt >= ntl) continue;
                    uint aaddr = pl1U + (uint)((base26[mt] + tapoff) * (P1CH * 2)) +
                                 (uint)(icc * 32) + ahi;
                    asm volatile("ldmatrix.sync.aligned.m8n8.x4.shared.b16 {%0,%1,%2,%3}, [%4];"
                                 : "=r"(a[mt][0]), "=r"(a[mt][1]), "=r"(a[mt][2]), "=r"(a[mt][3])
                                 : "r"(aaddr));
                }
                const uint4* fp = (const uint4*)g_w1f + (size_t)(c * 16 + ng * 4) * 32 + lane;
#pragma unroll
                for (int j = 0; j < 4; j++) {
                    uint4 v = __ldg(fp + j * 32);
#pragma unroll
                    for (int mt = 0; mt < 3; mt++) {
                        if (mt >= ntl) continue;
                        asm volatile("mma.sync.aligned.m16n8k16.row.col.f32.f16.f16.f32 "
                                     "{%0,%1,%2,%3}, {%4,%5,%6,%7}, {%8,%9}, {%0,%1,%2,%3};"
                                     : "+f"(d1[mt][2 * j][0]), "+f"(d1[mt][2 * j][1]),
                                       "+f"(d1[mt][2 * j][2]), "+f"(d1[mt][2 * j][3])
                                     : "r"(a[mt][0]), "r"(a[mt][1]), "r"(a[mt][2]), "r"(a[mt][3]),
                                       "r"(v.x), "r"(v.y));
                        asm volatile("mma.sync.aligned.m16n8k16.row.col.f32.f16.f16.f32 "
                                     "{%0,%1,%2,%3}, {%4,%5,%6,%7}, {%8,%9}, {%0,%1,%2,%3};"
                                     : "+f"(d1[mt][2 * j + 1][0]), "+f"(d1[mt][2 * j + 1][1]),
                                       "+f"(d1[mt][2 * j + 1][2]), "+f"(d1[mt][2 * j + 1][3])
                                     : "r"(a[mt][0]), "r"(a[mt][1]), "r"(a[mt][2]), "r"(a[mt][3]),
                                       "r"(v.z), "r"(v.w));
                    }
                }
            }
            __syncthreads();   // all reads of plane1 done before in-place h1 update

            // ---- epilogue B: gates -> c1 (SMEM), h1 -> plane1 ch32-95 (+global at s=6) ----
            __half* h1d = g_h1out + (size_t)b * PIX * HC1;
#pragma unroll
            for (int mt = 0; mt < 3; mt++) {
                if (mt >= ntl) continue;
                int tile = tbase + mt;
#pragma unroll
                for (int j = 0; j < 8; j++) {
                    float v0 = d1[mt][j][0], v1 = d1[mt][j][1], v2 = d1[mt][j][2], v3 = d1[mt][j][3];
                    float x0 = __shfl_xor_sync(0xffffffffu, v0, 1);
                    float x1 = __shfl_xor_sync(0xffffffffu, v1, 1);
                    float x2 = __shfl_xor_sync(0xffffffffu, v2, 1);
                    float x3 = __shfl_xor_sync(0xffffffffu, v3, 1);
                    int pixel = tile * 16 + r + odd * 8;
                    int hc = ng * 16 + j * 2 + (t >> 1);
                    float gi = odd ? x2 : v0;
                    float gf = odd ? x3 : v1;
                    float gc = odd ? v2 : x0;
                    float go = odd ? v3 : x1;
                    if (pixel < PIX) {
                        gi += __ldg(&bx1[hc]);
                        gf += __ldg(&bx1[64 + hc]);
                        gc += __ldg(&bx1[128 + hc]);
                        go += __ldg(&bx1[192 + hc]);
                        float cold = c1s[pixel * 65 + hc];
                        float w0 = __ldg(&Wc1[hc * PIX + pixel]);
                        float w1 = __ldg(&Wc1[10752 + hc * PIX + pixel]);
                        float w2 = __ldg(&Wc1[21504 + hc * PIX + pixel]);
                        float ci = sigf(gi + cold * w0);
                        float cf = sigf(gf + cold * w1);
                        float cc = cf * cold + ci * tanhf(gc);
                        float co = sigf(go + cc * w2);
                        c1s[pixel * 65 + hc] = cc;
                        __half hh = __float2half(co * tanhf(cc));
                        int y = pixel / WID, x = pixel % WID;
                        plane1[((y + 1) * P1ROW + (x + 1)) * P1CH + 32 + hc] = hh;
                        if (s == 6) h1d[pixel * HC1 + hc] = hh;
                    }
                }
            }
        }
        __syncthreads();   // h1_new visible before next step's phase B
    }
}

// ---------------- fc1 weight transpose: k follows [pix][ch] flatten ----------------
__global__ void k_wt(const float* __restrict__ fc1_w) {
    int idx = blockIdx.x * blockDim.x + threadIdx.x;
    if (idx >= 10752 * 64) return;
    int k = idx / 64, o = idx % 64;       // k = pix*64 + ch
    int pix = k / 64, ch = k % 64;
    g_fcwT[k * 64 + (o & 31) * 2 + (o >> 5)] = fc1_w[(size_t)o * 10752 + ch * PIX + pix];
}

// ---------------- fc1 head: out[:, 0:64] ----------------
__global__ void k_fc(const float* __restrict__ fc1_b, float* __restrict__ out) {
    __shared__ float shh[8 * 1344];
    int tid = threadIdx.x;
    int b0 = blockIdx.x * 8;
    int it = tid >> 5, o = tid & 31;
    float acc0 = 0.f, acc1 = 0.f;
    const __half* h1f = g_h1out;
#pragma unroll 1
    for (int cb = 0; cb < 8; cb++) {
        __syncthreads();
        for (int u = tid; u < 8 * 1344; u += 256) {
            int i2 = u / 1344, kk = u % 1344;
            shh[u] = __half2float(h1f[(size_t)(b0 + i2) * 10752 + cb * 1344 + kk]);
        }
        __syncthreads();
        const float* wp = g_fcwT + (size_t)cb * 1344 * 64 + o * 2;
        const float* hp = shh + it * 1344;
#pragma unroll 4
        for (int kk = 0; kk < 1344; kk++) {
            float hv = hp[kk];
            float2 w2 = __ldg((const float2*)(wp + (size_t)kk * 64));
            acc0 = fmaf(hv, w2.x, acc0);
            acc1 = fmaf(hv, w2.y, acc1);
        }
    }
    out[(size_t)(b0 + it) * 128 + o] = fmaxf(acc0 + fc1_b[o], 0.f);
    out[(size_t)(b0 + it) * 128 + o + 32] = fmaxf(acc1 + fc1_b[o + 32], 0.f);
}

// ---------------- exfc head: out[:, 64:128] ----------------
__global__ void k_exfc(const float* __restrict__ x_ex, const float* __restrict__ w,
                       const float* __restrict__ bias, float* __restrict__ out) {
    int idx = blockIdx.x * blockDim.x + threadIdx.x;
    if (idx >= BATCH * 64) return;
    int b = idx >> 6, o = idx & 63;
    float acc = bias[o];
#pragma unroll
    for (int k = 0; k < 24; k++) acc += x_ex[b * 24 + k] * __ldg(&w[o * 24 + k]);
    out[(size_t)b * 128 + 64 + o] = fmaxf(acc, 0.f);
}

// ---------------- launch ----------------
extern "C" void kernel_launch(void* const* d_in, const int* in_sizes, int n_in,
                              void* d_out, int out_size) {
    const float* input  = (const float*)d_in[0];
    const float* x_ex   = (const float*)d_in[1];
    const float* Wx0    = (const float*)d_in[2];
    const float* bx0    = (const float*)d_in[3];
    const float* Wh0    = (const float*)d_in[4];
    const float* Wc0    = (const float*)d_in[5];
    const float* Wx1    = (const float*)d_in[6];
    const float* bx1    = (const float*)d_in[7];
    const float* Wh1    = (const float*)d_in[8];
    const float* Wc1    = (const float*)d_in[9];
    const float* fc1_w  = (const float*)d_in[10];
    const float* fc1_b  = (const float*)d_in[11];
    const float* exfc_w = (const float*)d_in[12];
    const float* exfc_b = (const float*)d_in[13];
    float* out = (float*)d_out;

    (void)in_sizes; (void)n_in; (void)out_size;

    cudaFuncSetAttribute(k_cells, cudaFuncAttributeMaxDynamicSharedMemorySize, SMEM_TOT);

    k_gx0<<<BATCH, 256>>>(input, Wx0, bx0);
    k_wt<<<(10752 * 64 + 255) / 256, 256>>>(fc1_w);
    k_w0h<<<(NCH0 * 16 * 128 + 255) / 256, 256>>>(Wh0);
    k_w1h<<<(NCH1 * 16 * 256 + 255) / 256, 256>>>(Wx1, Wh1);
    k_w0f<<<(NCH0 * 8 * 32 * 4 + 255) / 256, 256>>>();
    k_w1f<<<(NCH1 * 16 * 32 * 4 + 255) / 256, 256>>>();

    k_cells<<<BATCH, 512, SMEM_TOT>>>(bx1, Wc0, Wc1);

    k_fc<<<BATCH / 8, 256>>>(fc1_b, out);
    k_exfc<<<(BATCH * 64 + 255) / 256, 256>>>(x_ex, exfc_w, exfc_b, out);
}

// round 16
// speedup vs baseline: 1.5866x; 1.1192x over previous
#include <cuda_runtime.h>
#include <cuda_fp16.h>
#include <math.h>

typedef unsigned long long ull;
typedef unsigned int uint;

#define BATCH 2048
#define HGT 7
#define WID 24
#define PIX 168            // 7*24
#define C0IN 2
#define HC0 32
#define HC1 64

// tensor-core geometry
#define P1ROW 26           // padded cols (24 + halo)
#define P1CH 96            // cell1 plane channels (32 h0 + 64 h1)
#define NCH1 54            // cell1: 9 taps * 6 ic16-chunks
#define NCH0 18            // cell0: 9 taps * 2 ic16-chunks

// persistent-kernel SMEM layout (bytes)
#define PL1_BYTES (9*P1ROW*P1CH*2)   // 44928
#define PL0_BYTES (9*P1ROW*HC0*2)    // 14976
#define C0_BYTES  (PIX*33*4)         // 22176 (pad 32->33: bank-conflict-free)
#define C1_BYTES  (PIX*65*4)         // 43680 (pad 64->65)
#define SMEM_TOT  (PL1_BYTES + PL0_BYTES + C0_BYTES + C1_BYTES)   // 125760

// ---------------- scratch ----------------
__device__ float  g_gx0[(size_t)BATCH * PIX * 128];     // [item][pix][hc*4+g], bias included
__device__ __half g_h1out[(size_t)BATCH * PIX * HC1];   // final h1, [item][pix][hc]
__device__ float  g_fcwT[10752 * 64];
__device__ __align__(16) __half g_w0h[NCH0 * 16 * 128]; // staging [chunk][k16][n]
__device__ __align__(16) __half g_w1h[NCH1 * 16 * 256];
// mma B-fragment layouts: [chunk][n8pair][lane][4 x b32]
__device__ __align__(16) uint g_w0f[NCH0 * 8 * 32 * 4];
__device__ __align__(16) uint g_w1f[NCH1 * 16 * 32 * 4];

// ---------------- helpers ----------------
// flag-independent fast transcendentals (MUFU EX2/RCP path via intrinsics)
__device__ __forceinline__ float sigf(float x) {
    return __fdividef(1.f, 1.f + __expf(-x));
}
__device__ __forceinline__ float tanhfast(float x) {
    float e = __expf(-2.f * x);
    return __fdividef(1.f - e, 1.f + e);
}
__device__ __forceinline__ uint smem_u32(const void* p) {
    uint a;
    asm("{ .reg .u64 t; cvta.to.shared.u64 t, %1; cvt.u32.u64 %0, t; }" : "=r"(a) : "l"(p));
    return a;
}

// ---------------- weight transforms (k-major staging layout) ----------------
__global__ void k_w0h(const float* __restrict__ Wh0) {
    int idx = blockIdx.x * blockDim.x + threadIdx.x;
    if (idx >= NCH0 * 16 * 128) return;
    int chunk = idx / 2048, rem = idx % 2048;
    int k = rem / 128, n = rem % 128;
    int tap = chunk >> 1, icc = chunk & 1;
    int ic = icc * 16 + k;
    int hc = n >> 2, g = n & 3;
    g_w0h[idx] = __float2half(Wh0[((g * HC0 + hc) * HC0 + ic) * 9 + tap]);
}

__global__ void k_w1h(const float* __restrict__ Wx1, const float* __restrict__ Wh1) {
    int idx = blockIdx.x * blockDim.x + threadIdx.x;
    if (idx >= NCH1 * 16 * 256) return;
    int chunk = idx / 4096, rem = idx % 4096;
    int k = rem / 256, n = rem % 256;
    int tap = chunk / 6, icc = chunk % 6;
    int ic = icc * 16 + k;
    int hc = n / 4, g = n % 4;
    float v = (ic < HC0) ? Wx1[((g * HC1 + hc) * HC0 + ic) * 9 + tap]
                         : Wh1[((g * HC1 + hc) * HC1 + (ic - HC0)) * 9 + tap];
    g_w1h[idx] = __float2half(v);
}

// ---------------- fragmentizers: k-major -> mma B-fragment order ----------------
__global__ void k_w0f() {
    int idx = blockIdx.x * blockDim.x + threadIdx.x;
    if (idx >= NCH0 * 8 * 32 * 4) return;
    int q = idx & 3, l = (idx >> 2) & 31, pp = (idx >> 7) & 7, c = idx >> 10;
    int tt = pp * 2 + (q >> 1), r = q & 1;
    int k0 = (l & 3) * 2 + r * 8, n = tt * 8 + (l >> 2);
    __half h0 = g_w0h[c * 2048 + k0 * 128 + n];
    __half h1 = g_w0h[c * 2048 + (k0 + 1) * 128 + n];
    ((__half2*)g_w0f)[idx] = __halves2half2(h0, h1);
}

__global__ void k_w1f() {
    int idx = blockIdx.x * blockDim.x + threadIdx.x;
    if (idx >= NCH1 * 16 * 32 * 4) return;
    int q = idx & 3, l = (idx >> 2) & 31, pp = (idx >> 7) & 15, c = idx >> 11;
    int tt = pp * 2 + (q >> 1), r = q & 1;
    int k0 = (l & 3) * 2 + r * 8, n = tt * 8 + (l >> 2);
    __half h0 = g_w1h[c * 4096 + k0 * 256 + n];
    __half h1 = g_w1h[c * 4096 + (k0 + 1) * 256 + n];
    ((__half2*)g_w1f)[idx] = __halves2half2(h0, h1);
}

// ---------------- gx0 = conv(input, Wx0) + bx0, layout [pix][hc*4+g] ----------------
#define SROW0 28
#define SPLANE0 (9*SROW0)
__global__ void k_gx0(const float* __restrict__ input, const float* __restrict__ Wx0,
                      const float* __restrict__ bx0) {
    __shared__ float sin_[C0IN * SPLANE0];
    int b = blockIdx.x, tid = threadIdx.x;
    for (int i = tid; i < C0IN * SPLANE0; i += blockDim.x) sin_[i] = 0.f;
    __syncthreads();
    for (int u = tid; u < C0IN * PIX; u += blockDim.x) {
        int ic = u / PIX, pix = u % PIX, y = pix / WID, x = pix % WID;
        sin_[ic * SPLANE0 + (y + 1) * SROW0 + (x + 1)] = input[(size_t)b * C0IN * PIX + u];
    }
    __syncthreads();
    for (int u = tid; u < 128 * PIX; u += blockDim.x) {
        int oc = u / PIX, pix = u % PIX, y = pix / WID, x = pix % WID;
        float acc = bx0[oc];
#pragma unroll
        for (int ic = 0; ic < C0IN; ic++)
#pragma unroll
            for (int ky = 0; ky < 3; ky++)
#pragma unroll
                for (int kx = 0; kx < 3; kx++)
                    acc += sin_[ic * SPLANE0 + (y + ky) * SROW0 + (x + kx)] *
                           __ldg(&Wx0[oc * 18 + ic * 9 + ky * 3 + kx]);
        int g = oc >> 5, hc = oc & 31;
        g_gx0[(size_t)b * PIX * 128 + pix * 128 + hc * 4 + g] = acc;
    }
}

// ---------------- persistent 7-step dual-layer cell kernel ----------------
__global__ void __launch_bounds__(512, 1)
k_cells(const float* __restrict__ bx1, const float* __restrict__ Wc0,
        const float* __restrict__ Wc1) {
    extern __shared__ __align__(16) char smraw[];
    __half* plane1 = (__half*)smraw;                                  // [9][26][96]
    __half* plane0 = (__half*)(smraw + PL1_BYTES);                    // [9][26][32]
    float*  c0s    = (float*)(smraw + PL1_BYTES + PL0_BYTES);         // [pix][33]
    float*  c1s    = (float*)(smraw + PL1_BYTES + PL0_BYTES + C0_BYTES); // [pix][65]

    int b = blockIdx.x, tid = threadIdx.x;
    int lane = tid & 31, warp = tid >> 5;
    int mg = warp >> 2, ng = warp & 3;

    // ---- zero entire SMEM state (planes incl. halos, c-states) once ----
    uint4 z4; z4.x = z4.y = z4.z = z4.w = 0u;
    for (int i = tid; i < SMEM_TOT / 16; i += 512) ((uint4*)smraw)[i] = z4;
    __syncthreads();

    uint pl1U = smem_u32(plane1);
    uint pl0U = smem_u32(plane0);

    int base26[3];
#pragma unroll
    for (int mt = 0; mt < 3; mt++) {
        int p = (mg * 3 + mt) * 16 + (lane & 15);
        if (p > 167) p = 167;
        base26[mt] = (p / WID + 1) * P1ROW + (p % WID + 1);
    }
    uint ahi = (uint)((lane >> 4) * 16);
    int t = lane & 3, r = lane >> 2, odd = t & 1;

    const float* gx0p = g_gx0 + (size_t)b * PIX * 128;

#pragma unroll 1
    for (int s = 0; s < 7; s++) {
        // ================= Phase A: layer 0 =================
        {
            float d0[3][4][4];
#pragma unroll
            for (int mt = 0; mt < 3; mt++)
#pragma unroll
                for (int j = 0; j < 4; j++)
#pragma unroll
                    for (int q = 0; q < 4; q++) d0[mt][j][q] = 0.f;

#pragma unroll 1
            for (int c = 0; c < NCH0; c++) {
                int tap = c >> 1, icc = c & 1;
                int tapoff = (tap / 3 - 1) * P1ROW + (tap % 3 - 1);
                uint a[3][4];
#pragma unroll
                for (int mt = 0; mt < 3; mt++) {
                    uint aaddr = pl0U + (uint)((base26[mt] + tapoff) * (HC0 * 2)) +
                                 (uint)(icc * 32) + ahi;
                    asm volatile("ldmatrix.sync.aligned.m8n8.x4.shared.b16 {%0,%1,%2,%3}, [%4];"
                                 : "=r"(a[mt][0]), "=r"(a[mt][1]), "=r"(a[mt][2]), "=r"(a[mt][3])
                                 : "r"(aaddr));
                }
                const uint4* fp = (const uint4*)g_w0f + (size_t)(c * 8 + ng * 2) * 32 + lane;
#pragma unroll
                for (int j = 0; j < 2; j++) {
                    uint4 v = __ldg(fp + j * 32);
#pragma unroll
                    for (int mt = 0; mt < 3; mt++) {
                        asm volatile("mma.sync.aligned.m16n8k16.row.col.f32.f16.f16.f32 "
                                     "{%0,%1,%2,%3}, {%4,%5,%6,%7}, {%8,%9}, {%0,%1,%2,%3};"
                                     : "+f"(d0[mt][2 * j][0]), "+f"(d0[mt][2 * j][1]),
                                       "+f"(d0[mt][2 * j][2]), "+f"(d0[mt][2 * j][3])
                                     : "r"(a[mt][0]), "r"(a[mt][1]), "r"(a[mt][2]), "r"(a[mt][3]),
                                       "r"(v.x), "r"(v.y));
                        asm volatile("mma.sync.aligned.m16n8k16.row.col.f32.f16.f16.f32 "
                                     "{%0,%1,%2,%3}, {%4,%5,%6,%7}, {%8,%9}, {%0,%1,%2,%3};"
                                     : "+f"(d0[mt][2 * j + 1][0]), "+f"(d0[mt][2 * j + 1][1]),
                                       "+f"(d0[mt][2 * j + 1][2]), "+f"(d0[mt][2 * j + 1][3])
                                     : "r"(a[mt][0]), "r"(a[mt][1]), "r"(a[mt][2]), "r"(a[mt][3]),
                                       "r"(v.z), "r"(v.w));
                    }
                }
            }
            __syncthreads();   // all reads of plane0 done before in-place h0 update

            // ---- epilogue A: gates -> c0 (SMEM), h0 -> plane0 + plane1 ch0-31 ----
#pragma unroll
            for (int mt = 0; mt < 3; mt++) {
                int tile = mg * 3 + mt;
#pragma unroll
                for (int j = 0; j < 4; j++) {
                    float v0 = d0[mt][j][0], v1 = d0[mt][j][1], v2 = d0[mt][j][2], v3 = d0[mt][j][3];
                    float x0 = __shfl_xor_sync(0xffffffffu, v0, 1);
                    float x1 = __shfl_xor_sync(0xffffffffu, v1, 1);
                    float x2 = __shfl_xor_sync(0xffffffffu, v2, 1);
                    float x3 = __shfl_xor_sync(0xffffffffu, v3, 1);
                    int pixel = tile * 16 + r + odd * 8;
                    int hc = ng * 8 + j * 2 + (t >> 1);
                    float gi = odd ? x2 : v0;
                    float gf = odd ? x3 : v1;
                    float gc = odd ? v2 : x0;
                    float go = odd ? v3 : x1;
                    if (pixel < PIX) {
                        float4 gx = __ldg((const float4*)(gx0p + pixel * 128 + hc * 4));
                        gi += gx.x; gf += gx.y; gc += gx.z; go += gx.w;
                        float cold = c0s[pixel * 33 + hc];
                        float w0 = __ldg(&Wc0[hc * PIX + pixel]);
                        float w1 = __ldg(&Wc0[HC0 * PIX + hc * PIX + pixel]);
                        float w2 = __ldg(&Wc0[2 * HC0 * PIX + hc * PIX + pixel]);
                        float ci = sigf(gi + cold * w0);
                        float cf = sigf(gf + cold * w1);
                        float cc = cf * cold + ci * tanhfast(gc);
                        float co = sigf(go + cc * w2);
                        c0s[pixel * 33 + hc] = cc;
                        __half hh = __float2half(co * tanhfast(cc));
                        int y = pixel / WID, x = pixel % WID;
                        int cell = (y + 1) * P1ROW + (x + 1);
                        plane0[cell * HC0 + hc] = hh;
                        plane1[cell * P1CH + hc] = hh;
                    }
                }
            }
        }
        __syncthreads();   // h0_new visible in plane1 before phase B reads

        // ================= Phase B: layer 1 =================
        {
            float d1[3][8][4];
#pragma unroll
            for (int mt = 0; mt < 3; mt++)
#pragma unroll
                for (int j = 0; j < 8; j++)
#pragma unroll
                    for (int q = 0; q < 4; q++) d1[mt][j][q] = 0.f;

#pragma unroll 1
            for (int c = 0; c < NCH1; c++) {
                int tap = c / 6, icc = c % 6;
                int tapoff = (tap / 3 - 1) * P1ROW + (tap % 3 - 1);
                uint a[3][4];
#pragma unroll
                for (int mt = 0; mt < 3; mt++) {
                    uint aaddr = pl1U + (uint)((base26[mt] + tapoff) * (P1CH * 2)) +
                                 (uint)(icc * 32) + ahi;
                    asm volatile("ldmatrix.sync.aligned.m8n8.x4.shared.b16 {%0,%1,%2,%3}, [%4];"
                                 : "=r"(a[mt][0]), "=r"(a[mt][1]), "=r"(a[mt][2]), "=r"(a[mt][3])
                                 : "r"(aaddr));
                }
                const uint4* fp = (const uint4*)g_w1f + (size_t)(c * 16 + ng * 4) * 32 + lane;
#pragma unroll
                for (int j = 0; j < 4; j++) {
                    uint4 v = __ldg(fp + j * 32);
#pragma unroll
                    for (int mt = 0; mt < 3; mt++) {
                        asm volatile("mma.sync.aligned.m16n8k16.row.col.f32.f16.f16.f32 "
                                     "{%0,%1,%2,%3}, {%4,%5,%6,%7}, {%8,%9}, {%0,%1,%2,%3};"
                                     : "+f"(d1[mt][2 * j][0]), "+f"(d1[mt][2 * j][1]),
                                       "+f"(d1[mt][2 * j][2]), "+f"(d1[mt][2 * j][3])
                                     : "r"(a[mt][0]), "r"(a[mt][1]), "r"(a[mt][2]), "r"(a[mt][3]),
                                       "r"(v.x), "r"(v.y));
                        asm volatile("mma.sync.aligned.m16n8k16.row.col.f32.f16.f16.f32 "
                                     "{%0,%1,%2,%3}, {%4,%5,%6,%7}, {%8,%9}, {%0,%1,%2,%3};"
                                     : "+f"(d1[mt][2 * j + 1][0]), "+f"(d1[mt][2 * j + 1][1]),
                                       "+f"(d1[mt][2 * j + 1][2]), "+f"(d1[mt][2 * j + 1][3])
                                     : "r"(a[mt][0]), "r"(a[mt][1]), "r"(a[mt][2]), "r"(a[mt][3]),
                                       "r"(v.z), "r"(v.w));
                    }
                }
            }
            __syncthreads();   // all reads of plane1 done before in-place h1 update

            // ---- epilogue B: gates -> c1 (SMEM), h1 -> plane1 ch32-95 (+global at s=6) ----
            __half* h1d = g_h1out + (size_t)b * PIX * HC1;
#pragma unroll
            for (int mt = 0; mt < 3; mt++) {
                int tile = mg * 3 + mt;
#pragma unroll
                for (int j = 0; j < 8; j++) {
                    float v0 = d1[mt][j][0], v1 = d1[mt][j][1], v2 = d1[mt][j][2], v3 = d1[mt][j][3];
                    float x0 = __shfl_xor_sync(0xffffffffu, v0, 1);
                    float x1 = __shfl_xor_sync(0xffffffffu, v1, 1);
                    float x2 = __shfl_xor_sync(0xffffffffu, v2, 1);
                    float x3 = __shfl_xor_sync(0xffffffffu, v3, 1);
                    int pixel = tile * 16 + r + odd * 8;
                    int hc = ng * 16 + j * 2 + (t >> 1);
                    float gi = odd ? x2 : v0;
                    float gf = odd ? x3 : v1;
                    float gc = odd ? v2 : x0;
                    float go = odd ? v3 : x1;
                    if (pixel < PIX) {
                        gi += __ldg(&bx1[hc]);
                        gf += __ldg(&bx1[64 + hc]);
                        gc += __ldg(&bx1[128 + hc]);
                        go += __ldg(&bx1[192 + hc]);
                        float cold = c1s[pixel * 65 + hc];
                        float w0 = __ldg(&Wc1[hc * PIX + pixel]);
                        float w1 = __ldg(&Wc1[10752 + hc * PIX + pixel]);
                        float w2 = __ldg(&Wc1[21504 + hc * PIX + pixel]);
                        float ci = sigf(gi + cold * w0);
                        float cf = sigf(gf + cold * w1);
                        float cc = cf * cold + ci * tanhfast(gc);
                        float co = sigf(go + cc * w2);
                        c1s[pixel * 65 + hc] = cc;
                        __half hh = __float2half(co * tanhfast(cc));
                        int y = pixel / WID, x = pixel % WID;
                        plane1[((y + 1) * P1ROW + (x + 1)) * P1CH + 32 + hc] = hh;
                        if (s == 6) h1d[pixel * HC1 + hc] = hh;
                    }
                }
            }
        }
        __syncthreads();   // h1_new visible before next step's phase B
    }
}

// ---------------- fc1 weight transpose: k follows [pix][ch] flatten ----------------
__global__ void k_wt(const float* __restrict__ fc1_w) {
    int idx = blockIdx.x * blockDim.x + threadIdx.x;
    if (idx >= 10752 * 64) return;
    int k = idx / 64, o = idx % 64;       // k = pix*64 + ch
    int pix = k / 64, ch = k % 64;
    g_fcwT[k * 64 + (o & 31) * 2 + (o >> 5)] = fc1_w[(size_t)o * 10752 + ch * PIX + pix];
}

// ---------------- fc1 head: out[:, 0:64] ----------------
__global__ void k_fc(const float* __restrict__ fc1_b, float* __restrict__ out) {
    __shared__ float shh[8 * 1344];
    int tid = threadIdx.x;
    int b0 = blockIdx.x * 8;
    int it = tid >> 5, o = tid & 31;
    float acc0 = 0.f, acc1 = 0.f;
    const __half* h1f = g_h1out;
#pragma unroll 1
    for (int cb = 0; cb < 8; cb++) {
        __syncthreads();
        for (int u = tid; u < 8 * 1344; u += 256) {
            int i2 = u / 1344, kk = u % 1344;
            shh[u] = __half2float(h1f[(size_t)(b0 + i2) * 10752 + cb * 1344 + kk]);
        }
        __syncthreads();
        const float* wp = g_fcwT + (size_t)cb * 1344 * 64 + o * 2;
        const float* hp = shh + it * 1344;
#pragma unroll 4
        for (int kk = 0; kk < 1344; kk++) {
            float hv = hp[kk];
            float2 w2 = __ldg((const float2*)(wp + (size_t)kk * 64));
            acc0 = fmaf(hv, w2.x, acc0);
            acc1 = fmaf(hv, w2.y, acc1);
        }
    }
    out[(size_t)(b0 + it) * 128 + o] = fmaxf(acc0 + fc1_b[o], 0.f);
    out[(size_t)(b0 + it) * 128 + o + 32] = fmaxf(acc1 + fc1_b[o + 32], 0.f);
}

// ---------------- exfc head: out[:, 64:128] ----------------
__global__ void k_exfc(const float* __restrict__ x_ex, const float* __restrict__ w,
                       const float* __restrict__ bias, float* __restrict__ out) {
    int idx = blockIdx.x * blockDim.x + threadIdx.x;
    if (idx >= BATCH * 64) return;
    int b = idx >> 6, o = idx & 63;
    float acc = bias[o];
#pragma unroll
    for (int k = 0; k < 24; k++) acc += x_ex[b * 24 + k] * __ldg(&w[o * 24 + k]);
    out[(size_t)b * 128 + 64 + o] = fmaxf(acc, 0.f);
}

// ---------------- launch ----------------
extern "C" void kernel_launch(void* const* d_in, const int* in_sizes, int n_in,
                              void* d_out, int out_size) {
    const float* input  = (const float*)d_in[0];
    const float* x_ex   = (const float*)d_in[1];
    const float* Wx0    = (const float*)d_in[2];
    const float* bx0    = (const float*)d_in[3];
    const float* Wh0    = (const float*)d_in[4];
    const float* Wc0    = (const float*)d_in[5];
    const float* Wx1    = (const float*)d_in[6];
    const float* bx1    = (const float*)d_in[7];
    const float* Wh1    = (const float*)d_in[8];
    const float* Wc1    = (const float*)d_in[9];
    const float* fc1_w  = (const float*)d_in[10];
    const float* fc1_b  = (const float*)d_in[11];
    const float* exfc_w = (const float*)d_in[12];
    const float* exfc_b = (const float*)d_in[13];
    float* out = (float*)d_out;

    (void)in_sizes; (void)n_in; (void)out_size;

    cudaFuncSetAttribute(k_cells, cudaFuncAttributeMaxDynamicSharedMemorySize, SMEM_TOT);

    k_gx0<<<BATCH, 256>>>(input, Wx0, bx0);
    k_wt<<<(10752 * 64 + 255) / 256, 256>>>(fc1_w);
    k_w0h<<<(NCH0 * 16 * 128 + 255) / 256, 256>>>(Wh0);
    k_w1h<<<(NCH1 * 16 * 256 + 255) / 256, 256>>>(Wx1, Wh1);
    k_w0f<<<(NCH0 * 8 * 32 * 4 + 255) / 256, 256>>>();
    k_w1f<<<(NCH1 * 16 * 32 * 4 + 255) / 256, 256>>>();

    k_cells<<<BATCH, 512, SMEM_TOT>>>(bx1, Wc0, Wc1);

    k_fc<<<BATCH / 8, 256>>>(fc1_b, out);
    k_exfc<<<(BATCH * 64 + 255) / 256, 256>>>(x_ex, exfc_w, exfc_b, out);
}